// round 8
// baseline (speedup 1.0000x reference)
#include <cuda_runtime.h>
#include <cstdint>
#include <math.h>

#define NN      100000
#define NE_MAX  1600000
#define IN_DIM  512
#define OUT_DIM 128
#define NBLK_SCAN 196                 // ceil(NN/512)

// ---------------------------------------------------------------------------
// Scratch. g_zero cleared by one memset per call:
//   [0,2NN) int outdeg | [2NN,4NN) int indeg | 1024 f wf | 256 f cpre | 4 bar
// ---------------------------------------------------------------------------
#define OFF_IND  (2 * NN)
#define OFF_WF   (4 * NN)
#define OFF_CPRE (4 * NN + 1024)
#define OFF_BAR  (4 * NN + 1024 + 256)
#define ZERO_INTS (4 * NN + 1024 + 256 + 4)
__device__ int   g_zero[ZERO_INTS];
__device__ int   g_S   [2 * NN];         // per-list inclusive scan of indeg
__device__ int   g_cur [2 * NN];         // scatter cursors (row starts)
__device__ int   g_csr [2 * NE_MAX];     // src ids grouped by dst, per list
__device__ int   g_bsums[2 * NBLK_SCAN];
__device__ float g_v   [2 * OUT_DIM];
__device__ float g_u   [2 * IN_DIM];
__device__ float g_k   [2];
__device__ float g_p   [4 * NN];         // pfa, pfb, psa, psb

// ---------------------------------------------------------------------------
// Grid barrier (counter pre-zeroed by memset)
// ---------------------------------------------------------------------------
__device__ __forceinline__ void grid_bar(int* cnt, int nblocks) {
    __threadfence();
    __syncthreads();
    if (threadIdx.x == 0) {
        atomicAdd(cnt, 1);
        while (*(volatile int*)cnt < nblocks) {}
    }
    __syncthreads();
}

// ---------------------------------------------------------------------------
// 4-way histogram: y=0: src1->outdeg, y=1: src2->outdeg+NN,
//                  y=2: dst1->indeg,  y=3: dst2->indeg+NN
// ---------------------------------------------------------------------------
__global__ void hist4way(const int* __restrict__ src1, int ne1,
                         const int* __restrict__ src2, int ne2,
                         const int* __restrict__ dst1,
                         const int* __restrict__ dst2,
                         int* __restrict__ outdeg, int* __restrict__ indeg)
{
    const int* idx; int ne; int* dg;
    switch (blockIdx.y) {
        case 0: idx = src1; ne = ne1; dg = outdeg;      break;
        case 1: idx = src2; ne = ne2; dg = outdeg + NN; break;
        case 2: idx = dst1; ne = ne1; dg = indeg;       break;
        default: idx = dst2; ne = ne2; dg = indeg + NN; break;
    }
    int e0 = (blockIdx.x * blockDim.x + threadIdx.x) * 4;
    if (e0 + 3 < ne) {
        int4 s = *(const int4*)(idx + e0);
        atomicAdd(&dg[s.x], 1);
        atomicAdd(&dg[s.y], 1);
        atomicAdd(&dg[s.z], 1);
        atomicAdd(&dg[s.w], 1);
    } else {
        for (int e = e0; e < ne; e++) atomicAdd(&dg[idx[e]], 1);
    }
}

// ---------------------------------------------------------------------------
// Fused per-list scan over INDEG: 392 blocks x 512 thr, one grid barrier.
// ---------------------------------------------------------------------------
__global__ __launch_bounds__(512) void scan_kernel(
    const int* __restrict__ indeg, int* __restrict__ S, int* __restrict__ cur,
    int* __restrict__ bsums, int* __restrict__ bar, int n)
{
    __shared__ int tmp[512];
    __shared__ int red[16];
    int list = blockIdx.x / NBLK_SCAN;
    int lb   = blockIdx.x % NBLK_SCAN;
    int t = threadIdx.x;
    int g = lb * 512 + t;
    const int* dg = indeg + list * NN;
    int dv = (g < n) ? dg[g] : 0;

    // block inclusive scan
    tmp[t] = dv;
    __syncthreads();
    #pragma unroll
    for (int off = 1; off < 512; off <<= 1) {
        int x = (t >= off) ? tmp[t - off] : 0;
        __syncthreads();
        tmp[t] += x;
        __syncthreads();
    }
    int local = tmp[t];
    if (t == 511) bsums[list * NBLK_SCAN + lb] = tmp[511];

    grid_bar(&bar[2], 2 * NBLK_SCAN);

    // per-block offset = sum of earlier blocks' totals (lb <= 195 < 512)
    int part = (t < lb) ? bsums[list * NBLK_SCAN + t] : 0;
    #pragma unroll
    for (int o = 16; o; o >>= 1) part += __shfl_xor_sync(0xffffffffu, part, o);
    if ((t & 31) == 0) red[t >> 5] = part;
    __syncthreads();
    if (t < 16) {
        int x = red[t];
        #pragma unroll
        for (int o = 8; o; o >>= 1) x += __shfl_xor_sync(0xffffu, x, o);
        if (t == 0) red[0] = x;
    }
    __syncthreads();
    int off = red[0];

    if (g < n) {
        int s = local + off;
        S[list * NN + g] = s;
        cur[list * NN + g] = s - dv;
    }
}

// ---------------------------------------------------------------------------
// wf body (grid-stride over GWF blocks), weights = OUTDEG
// ---------------------------------------------------------------------------
__device__ __forceinline__ void wf_body(
    const float* __restrict__ feat, const int* __restrict__ deg1,
    const int* __restrict__ deg2, float* __restrict__ wf, int n, int b, int GWF)
{
    __shared__ float red[256 * 8];
    int t = threadIdx.x;
    int half = t >> 7, c = t & 127;
    const float4* f4 = (const float4*)feat;

    float4 a1 = make_float4(0.f, 0.f, 0.f, 0.f);
    float4 a2 = make_float4(0.f, 0.f, 0.f, 0.f);
    for (int v = b * 2 + half; v < n; v += GWF * 2) {
        float w1 = (float)__ldg(&deg1[v]);
        float w2 = (float)__ldg(&deg2[v]);
        float4 x = __ldg(&f4[(size_t)v * 128 + c]);
        a1.x += w1 * x.x; a1.y += w1 * x.y; a1.z += w1 * x.z; a1.w += w1 * x.w;
        a2.x += w2 * x.x; a2.y += w2 * x.y; a2.z += w2 * x.z; a2.w += w2 * x.w;
    }
    *(float4*)&red[t * 8]     = a1;
    *(float4*)&red[t * 8 + 4] = a2;
    __syncthreads();
    if (half == 0) {
        int p = (t + 128) * 8;
        a1.x += red[p];     a1.y += red[p + 1]; a1.z += red[p + 2]; a1.w += red[p + 3];
        a2.x += red[p + 4]; a2.y += red[p + 5]; a2.z += red[p + 6]; a2.w += red[p + 7];
        atomicAdd(&wf[c * 4],     a1.x);
        atomicAdd(&wf[c * 4 + 1], a1.y);
        atomicAdd(&wf[c * 4 + 2], a1.z);
        atomicAdd(&wf[c * 4 + 3], a1.w);
        atomicAdd(&wf[IN_DIM + c * 4],     a2.x);
        atomicAdd(&wf[IN_DIM + c * 4 + 1], a2.y);
        atomicAdd(&wf[IN_DIM + c * 4 + 2], a2.z);
        atomicAdd(&wf[IN_DIM + c * 4 + 3], a2.w);
    }
}

// ---------------------------------------------------------------------------
// CSR permute body: csr[cur[dst[e]]++] = src[e]   (cursors from INDEG scan)
// ---------------------------------------------------------------------------
__device__ __forceinline__ void permute_block(
    const int* __restrict__ src, const int* __restrict__ dst,
    int* __restrict__ cur, int* __restrict__ csr, int bx, int ne)
{
    int e0 = (bx * 256 + threadIdx.x) * 4;
    if (e0 + 3 < ne) {
        int4 s = *(const int4*)(src + e0);
        int4 d = *(const int4*)(dst + e0);
        csr[atomicAdd(&cur[d.x], 1)] = s.x;
        csr[atomicAdd(&cur[d.y], 1)] = s.y;
        csr[atomicAdd(&cur[d.z], 1)] = s.z;
        csr[atomicAdd(&cur[d.w], 1)] = s.w;
    } else {
        for (int e = e0; e < ne; e++)
            csr[atomicAdd(&cur[dst[e]], 1)] = src[e];
    }
}

// ---------------------------------------------------------------------------
// Fused wf (blocks [0,GWF)) + CSR permute (both lists) in one grid.
// ---------------------------------------------------------------------------
__global__ __launch_bounds__(256) void wf_csr_kernel(
    const float* __restrict__ feat, const int* __restrict__ outdeg,
    float* __restrict__ wf,
    const int* __restrict__ src1, const int* __restrict__ dst1, int ne1,
    const int* __restrict__ src2, const int* __restrict__ dst2, int ne2,
    int* __restrict__ cur, int* __restrict__ csr, int n, int GWF, int gp1)
{
    int b = blockIdx.x;
    if (b < GWF) {
        wf_body(feat, outdeg, outdeg + NN, wf, n, b, GWF);
    } else if (b < GWF + gp1) {
        permute_block(src1, dst1, cur, csr, b - GWF, ne1);
    } else {
        permute_block(src2, dst2, cur + NN, csr + NE_MAX, b - GWF - gp1, ne2);
    }
}

// ---------------------------------------------------------------------------
// Fused small chain: cpre -> v -> u, kc (grid barriers).
// ---------------------------------------------------------------------------
__global__ __launch_bounds__(128) void chain_kernel(
    const float* __restrict__ W1, const float* __restrict__ W2,
    const float* __restrict__ Wb, const float* __restrict__ b1,
    const float* __restrict__ b2, const float* __restrict__ bb,
    const float* __restrict__ wf, float* __restrict__ cpre,
    float* __restrict__ v, float* __restrict__ u, float* __restrict__ kc,
    int* __restrict__ bar, float inv_n)
{
    int b = blockIdx.x;          // 0..127
    int t = threadIdx.x;         // 0..127
    int warp = t >> 5, lane = t & 31;

    {
        int hh = b >> 6, chunk = b & 63;
        const float* W = hh ? W2 : W1;
        const float* w = wf + hh * IN_DIM + chunk * 8;
        const float* Wc = W + (size_t)(chunk * 8) * OUT_DIM + t;
        float s = 0.f;
        #pragma unroll
        for (int k = 0; k < 8; k++)
            s += __ldg(&w[k]) * __ldg(&Wc[k * OUT_DIM]);
        atomicAdd(&cpre[hh * OUT_DIM + t], s);
    }
    grid_bar(&bar[0], 128);

    if (b < 64) {
        int gw = b * 4 + warp;
        int half = gw >> 7, d = gw & 127;
        const float* bh = half ? b2 : b1;
        const float* cp = cpre + half * OUT_DIM;
        const float* wr = Wb + (size_t)d * OUT_DIM;
        float s = 0.f;
        #pragma unroll
        for (int j = 0; j < 4; j++) {
            int e = lane + 32 * j;
            float c = 1.0f / (1.0f + expf(-(__ldcg(&cp[e]) * inv_n + __ldg(&bh[e]))));
            s += __ldg(&wr[e]) * c;
        }
        #pragma unroll
        for (int o = 16; o; o >>= 1) s += __shfl_xor_sync(0xffffffffu, s, o);
        if (lane == 0) v[half * OUT_DIM + d] = s;
    }
    grid_bar(&bar[1], 128);

    int W512 = b * 4 + warp;     // 0..511
    #pragma unroll
    for (int rep = 0; rep < 2; rep++) {
        int idx = W512 + rep * 512;
        int half = idx >> 9;
        int tt = idx & 511;
        const float* W = half ? W1 : W2;
        const float* vv = v + half * OUT_DIM;
        const float* wr = W + (size_t)tt * OUT_DIM;
        float s = 0.f;
        #pragma unroll
        for (int j = 0; j < 4; j++) {
            int d = lane + 32 * j;
            s += __ldg(&wr[d]) * __ldcg(&vv[d]);
        }
        #pragma unroll
        for (int o = 16; o; o >>= 1) s += __shfl_xor_sync(0xffffffffu, s, o);
        if (lane == 0) u[half * IN_DIM + tt] = s;
    }
    if (W512 < 2) {
        const float* bv = W512 ? b1 : b2;
        const float* vv = v + W512 * OUT_DIM;
        float s = 0.f;
        #pragma unroll
        for (int j = 0; j < 4; j++) {
            int d = lane + 32 * j;
            s += __ldg(&bv[d]) * __ldcg(&vv[d]);
        }
        #pragma unroll
        for (int o = 16; o; o >>= 1) s += __shfl_xor_sync(0xffffffffu, s, o);
        if (lane == 0) kc[W512] = s + __ldg(bb);
    }
}

// ---------------------------------------------------------------------------
// p body: warp-per-node dot with u_a and u_b.
// ---------------------------------------------------------------------------
__device__ __forceinline__ void p_block(
    const float* __restrict__ X, const float* __restrict__ u,
    float* __restrict__ pa, float* __restrict__ pb, int node_base, int n)
{
    __shared__ __align__(16) float su[2 * IN_DIM];
    for (int i = threadIdx.x; i < 2 * IN_DIM; i += 256) su[i] = u[i];
    __syncthreads();
    int warp = threadIdx.x >> 5, lane = threadIdx.x & 31;
    int v = node_base + warp;
    if (v >= n) return;
    const float4* x4 = (const float4*)(X + (size_t)v * IN_DIM);
    const float4* ua4 = (const float4*)su;
    const float4* ub4 = (const float4*)(su + IN_DIM);
    float sa = 0.f, sb = 0.f;
    #pragma unroll
    for (int j = 0; j < 4; j++) {
        float4 x = x4[lane + 32 * j];
        float4 a = ua4[lane + 32 * j];
        float4 b = ub4[lane + 32 * j];
        sa += x.x * a.x + x.y * a.y + x.z * a.z + x.w * a.w;
        sb += x.x * b.x + x.y * b.y + x.z * b.z + x.w * b.w;
    }
    #pragma unroll
    for (int o = 16; o; o >>= 1) {
        sa += __shfl_xor_sync(0xffffffffu, sa, o);
        sb += __shfl_xor_sync(0xffffffffu, sb, o);
    }
    if (lane == 0) { pa[v] = sa; pb[v] = sb; }
}

// ---------------------------------------------------------------------------
// Gather body: out[d] = k + sum_{e in row d} p[csr[e]]   (thread per node)
// ---------------------------------------------------------------------------
__device__ __forceinline__ void gather_block(
    const int* __restrict__ S, const int* __restrict__ csr,
    const float* __restrict__ p, float* __restrict__ out,
    const float* __restrict__ kp, int bx, int n)
{
    int d = bx * 256 + threadIdx.x;
    if (d >= n) return;
    int s0 = (d == 0) ? 0 : __ldg(&S[d - 1]);
    int s1 = __ldg(&S[d]);
    float sum = 0.f;
    #pragma unroll 4
    for (int e = s0; e < s1; e++)
        sum += __ldg(&p[__ldg(&csr[e])]);
    out[d] = sum + __ldg(kp);
}

// ---------------------------------------------------------------------------
// Stage: p_feat only (needs u).
// ---------------------------------------------------------------------------
__global__ __launch_bounds__(256) void pfeat_kernel(
    const float* __restrict__ feat, const float* __restrict__ u,
    float* __restrict__ pp, int n)
{
    p_block(feat, u, pp, pp + NN, blockIdx.x * 8, n);
}

// ---------------------------------------------------------------------------
// Stage: gather feat quarters (q0: csr2/pfa, q1: csr1/pfb) || p_shuf.
// ---------------------------------------------------------------------------
__global__ __launch_bounds__(256) void gatherfeat_pshuf_kernel(
    const float* __restrict__ shuf, const float* __restrict__ u,
    float* __restrict__ pp, float* __restrict__ out,
    const int* __restrict__ S, const int* __restrict__ csr,
    const float* __restrict__ kc, int n, int GQ)
{
    int b = blockIdx.x;
    if (b < GQ) {
        gather_block(S + NN, csr + NE_MAX, pp, out, &kc[0], b, n);          // q0
    } else if (b < 2 * GQ) {
        gather_block(S, csr, pp + NN, out + n, &kc[1], b - GQ, n);          // q1
    } else {
        p_block(shuf, u, pp + 2 * NN, pp + 3 * NN, (b - 2 * GQ) * 8, n);
    }
}

// ---------------------------------------------------------------------------
// Stage: gather shuf quarters (q2: csr2/psa, q3: csr1/psb).
// ---------------------------------------------------------------------------
__global__ __launch_bounds__(256) void gathershuf_kernel(
    const float* __restrict__ pp, float* __restrict__ out,
    const int* __restrict__ S, const int* __restrict__ csr,
    const float* __restrict__ kc, int n, int GQ)
{
    int b = blockIdx.x;
    if (b < GQ)
        gather_block(S + NN, csr + NE_MAX, pp + 2 * NN, out + 2 * n, &kc[0], b, n);
    else
        gather_block(S, csr, pp + 3 * NN, out + 3 * n, &kc[1], b - GQ, n);
}

// ---------------------------------------------------------------------------
// Launch
// ---------------------------------------------------------------------------
extern "C" void kernel_launch(void* const* d_in, const int* in_sizes, int n_in,
                              void* d_out, int out_size)
{
    const float* feat = (const float*)d_in[0];
    const float* shuf = (const float*)d_in[1];
    const int*   src1 = (const int*)d_in[2];
    const int*   dst1 = (const int*)d_in[3];
    const int*   src2 = (const int*)d_in[4];
    const int*   dst2 = (const int*)d_in[5];
    const float* W1   = (const float*)d_in[6];
    const float* b1   = (const float*)d_in[7];
    const float* W2   = (const float*)d_in[8];
    const float* b2   = (const float*)d_in[9];
    const float* Wb   = (const float*)d_in[10];
    const float* bb   = (const float*)d_in[11];
    float* out = (float*)d_out;

    const int n   = in_sizes[0] / IN_DIM;   // 100000
    const int ne1 = in_sizes[2];
    const int ne2 = in_sizes[4];

    void* p;
    cudaGetSymbolAddress(&p, g_zero);
    int*   outdeg = (int*)p;
    int*   indeg  = (int*)p + OFF_IND;
    float* wf     = (float*)((int*)p + OFF_WF);
    float* cpre   = (float*)((int*)p + OFF_CPRE);
    int*   bar    = (int*)p + OFF_BAR;
    cudaGetSymbolAddress(&p, g_S);     int*   S    = (int*)p;
    cudaGetSymbolAddress(&p, g_cur);   int*   cur  = (int*)p;
    cudaGetSymbolAddress(&p, g_csr);   int*   csr  = (int*)p;
    cudaGetSymbolAddress(&p, g_bsums); int*   bs   = (int*)p;
    cudaGetSymbolAddress(&p, g_v);     float* v    = (float*)p;
    cudaGetSymbolAddress(&p, g_u);     float* u    = (float*)p;
    cudaGetSymbolAddress(&p, g_k);     float* kc   = (float*)p;
    cudaGetSymbolAddress(&p, g_p);     float* pp   = (float*)p;

    // 0) zero outdeg+indeg+wf+cpre+barriers
    cudaMemsetAsync(outdeg, 0, ZERO_INTS * sizeof(int));

    // 1) 4-way histograms (src -> outdeg for wf, dst -> indeg for CSR)
    int gp1 = (ne1 / 4 + 255) / 256, gp2 = (ne2 / 4 + 255) / 256;
    {
        dim3 grid(gp1 > gp2 ? gp1 : gp2, 4);
        hist4way<<<grid, 256>>>(src1, ne1, src2, ne2, dst1, dst2, outdeg, indeg);
    }

    // 2) per-list scans of indeg -> S, cur
    scan_kernel<<<2 * NBLK_SCAN, 512>>>(indeg, S, cur, bs, bar, n);

    // 3) wf (512 grid-stride blocks) || CSR permute (both lists)
    wf_csr_kernel<<<512 + gp1 + gp2, 256>>>(
        feat, outdeg, wf, src1, dst1, ne1, src2, dst2, ne2, cur, csr, n, 512, gp1);

    // 4) fused tiny chain -> u, kc
    chain_kernel<<<128, 128>>>(W1, W2, Wb, b1, b2, bb, wf, cpre, v, u, kc,
                               bar, 1.0f / (float)n);

    // 5) p_feat
    int G_PF = (n + 7) / 8;               // 12500
    pfeat_kernel<<<G_PF, 256>>>(feat, u, pp, n);

    // 6) gather feat quarters || p_shuf
    int GQ = (n + 255) / 256;             // 391
    gatherfeat_pshuf_kernel<<<2 * GQ + G_PF, 256>>>(
        shuf, u, pp, out, S, csr, kc, n, GQ);

    // 7) gather shuf quarters
    gathershuf_kernel<<<2 * GQ, 256>>>(pp, out, S, csr, kc, n, GQ);
}

// round 9
// speedup vs baseline: 1.1887x; 1.1887x over previous
#include <cuda_runtime.h>
#include <cstdint>
#include <math.h>

#define NN      100000
#define IN_DIM  512
#define OUT_DIM 128

// ---------------------------------------------------------------------------
// Scratch. g_zero cleared by one memset per call:
//   [0,2NN) int outdeg | 1024 f wf | 256 f cpre | 4 int bar |
//   [aligned] 2NN float2 accA | 2NN float2 accB   (as 4NN floats each? no:)
//   accA: NN float2 (q0,q2), accB: NN float2 (q1,q3) -> 4NN floats total
// ---------------------------------------------------------------------------
#define OFF_WF   (2 * NN)
#define OFF_CPRE (2 * NN + 1024)
#define OFF_BAR  (2 * NN + 1024 + 256)
#define OFF_ACC  (2 * NN + 1024 + 256 + 4)      // 805136 B offset, 8B aligned
#define ZERO_INTS (OFF_ACC + 4 * NN)
__device__ __align__(16) int g_zero[ZERO_INTS];
__device__ float  g_v [2 * OUT_DIM];
__device__ float  g_u [2 * IN_DIM];
__device__ float  g_k [2];
__device__ float4 g_p4[NN];                      // (pfa, pfb, psa, psb)

// ---------------------------------------------------------------------------
// Grid barrier (counter pre-zeroed by memset)
// ---------------------------------------------------------------------------
__device__ __forceinline__ void grid_bar(int* cnt, int nblocks) {
    __threadfence();
    __syncthreads();
    if (threadIdx.x == 0) {
        atomicAdd(cnt, 1);
        while (*(volatile int*)cnt < nblocks) {}
    }
    __syncthreads();
}

// ---------------------------------------------------------------------------
// Vector reduction: acc[0] += a, acc[1] += b  (sm_90+ red.global.add.v2.f32)
// ---------------------------------------------------------------------------
__device__ __forceinline__ void red_v2(float2* addr, float a, float b) {
    asm volatile("red.global.add.v2.f32 [%0], {%1, %2};"
                 :: "l"(addr), "f"(a), "f"(b) : "memory");
}

// ---------------------------------------------------------------------------
// Histogram over both src lists (blockIdx.y selects list).
// ---------------------------------------------------------------------------
__global__ void hist_both(const int* __restrict__ srcA, int neA,
                          const int* __restrict__ srcB, int neB,
                          int* __restrict__ deg)
{
    const int* src = blockIdx.y ? srcB : srcA;
    int ne = blockIdx.y ? neB : neA;
    int* dg = deg + blockIdx.y * NN;
    int e0 = (blockIdx.x * blockDim.x + threadIdx.x) * 4;
    if (e0 + 3 < ne) {
        int4 s = *(const int4*)(src + e0);
        atomicAdd(&dg[s.x], 1);
        atomicAdd(&dg[s.y], 1);
        atomicAdd(&dg[s.z], 1);
        atomicAdd(&dg[s.w], 1);
    } else {
        for (int e = e0; e < ne; e++) atomicAdd(&dg[src[e]], 1);
    }
}

// ---------------------------------------------------------------------------
// wf[c] = sum_v deg1[v]*feat[v,c] ; wf[512+c] = sum_v deg2[v]*feat[v,c]
// ---------------------------------------------------------------------------
__global__ __launch_bounds__(256) void wf_kernel(
    const float* __restrict__ feat, const int* __restrict__ deg1,
    const int* __restrict__ deg2, float* __restrict__ wf, int n)
{
    __shared__ float red[256 * 8];
    int t = threadIdx.x;
    int half = t >> 7, c = t & 127;
    const float4* f4 = (const float4*)feat;

    float4 a1 = make_float4(0.f, 0.f, 0.f, 0.f);
    float4 a2 = make_float4(0.f, 0.f, 0.f, 0.f);
    for (int v = blockIdx.x * 2 + half; v < n; v += gridDim.x * 2) {
        float w1 = (float)__ldg(&deg1[v]);
        float w2 = (float)__ldg(&deg2[v]);
        float4 x = __ldg(&f4[(size_t)v * 128 + c]);
        a1.x += w1 * x.x; a1.y += w1 * x.y; a1.z += w1 * x.z; a1.w += w1 * x.w;
        a2.x += w2 * x.x; a2.y += w2 * x.y; a2.z += w2 * x.z; a2.w += w2 * x.w;
    }
    *(float4*)&red[t * 8]     = a1;
    *(float4*)&red[t * 8 + 4] = a2;
    __syncthreads();
    if (half == 0) {
        int p = (t + 128) * 8;
        a1.x += red[p];     a1.y += red[p + 1]; a1.z += red[p + 2]; a1.w += red[p + 3];
        a2.x += red[p + 4]; a2.y += red[p + 5]; a2.z += red[p + 6]; a2.w += red[p + 7];
        atomicAdd(&wf[c * 4],     a1.x);
        atomicAdd(&wf[c * 4 + 1], a1.y);
        atomicAdd(&wf[c * 4 + 2], a1.z);
        atomicAdd(&wf[c * 4 + 3], a1.w);
        atomicAdd(&wf[IN_DIM + c * 4],     a2.x);
        atomicAdd(&wf[IN_DIM + c * 4 + 1], a2.y);
        atomicAdd(&wf[IN_DIM + c * 4 + 2], a2.z);
        atomicAdd(&wf[IN_DIM + c * 4 + 3], a2.w);
    }
}

// ---------------------------------------------------------------------------
// Fused small chain: cpre -> v -> u, kc (grid barriers). 128 blocks x 128.
// ---------------------------------------------------------------------------
__global__ __launch_bounds__(128) void chain_kernel(
    const float* __restrict__ W1, const float* __restrict__ W2,
    const float* __restrict__ Wb, const float* __restrict__ b1,
    const float* __restrict__ b2, const float* __restrict__ bb,
    const float* __restrict__ wf, float* __restrict__ cpre,
    float* __restrict__ v, float* __restrict__ u, float* __restrict__ kc,
    int* __restrict__ bar, float inv_n)
{
    int b = blockIdx.x;          // 0..127
    int t = threadIdx.x;         // 0..127
    int warp = t >> 5, lane = t & 31;

    {
        int hh = b >> 6, chunk = b & 63;
        const float* W = hh ? W2 : W1;
        const float* w = wf + hh * IN_DIM + chunk * 8;
        const float* Wc = W + (size_t)(chunk * 8) * OUT_DIM + t;
        float s = 0.f;
        #pragma unroll
        for (int k = 0; k < 8; k++)
            s += __ldg(&w[k]) * __ldg(&Wc[k * OUT_DIM]);
        atomicAdd(&cpre[hh * OUT_DIM + t], s);
    }
    grid_bar(&bar[0], 128);

    if (b < 64) {
        int gw = b * 4 + warp;
        int half = gw >> 7, d = gw & 127;
        const float* bh = half ? b2 : b1;
        const float* cp = cpre + half * OUT_DIM;
        const float* wr = Wb + (size_t)d * OUT_DIM;
        float s = 0.f;
        #pragma unroll
        for (int j = 0; j < 4; j++) {
            int e = lane + 32 * j;
            float c = 1.0f / (1.0f + expf(-(__ldcg(&cp[e]) * inv_n + __ldg(&bh[e]))));
            s += __ldg(&wr[e]) * c;
        }
        #pragma unroll
        for (int o = 16; o; o >>= 1) s += __shfl_xor_sync(0xffffffffu, s, o);
        if (lane == 0) v[half * OUT_DIM + d] = s;
    }
    grid_bar(&bar[1], 128);

    int W512 = b * 4 + warp;     // 0..511
    #pragma unroll
    for (int rep = 0; rep < 2; rep++) {
        int idx = W512 + rep * 512;
        int half = idx >> 9;                 // 0: u_a (W2,v1)  1: u_b (W1,v2)
        int tt = idx & 511;
        const float* W = half ? W1 : W2;
        const float* vv = v + half * OUT_DIM;
        const float* wr = W + (size_t)tt * OUT_DIM;
        float s = 0.f;
        #pragma unroll
        for (int j = 0; j < 4; j++) {
            int d = lane + 32 * j;
            s += __ldg(&wr[d]) * __ldcg(&vv[d]);
        }
        #pragma unroll
        for (int o = 16; o; o >>= 1) s += __shfl_xor_sync(0xffffffffu, s, o);
        if (lane == 0) u[half * IN_DIM + tt] = s;
    }
    if (W512 < 2) {                          // kc[0]=b2.v1+bb, kc[1]=b1.v2+bb
        const float* bv = W512 ? b1 : b2;
        const float* vv = v + W512 * OUT_DIM;
        float s = 0.f;
        #pragma unroll
        for (int j = 0; j < 4; j++) {
            int d = lane + 32 * j;
            s += __ldg(&bv[d]) * __ldcg(&vv[d]);
        }
        #pragma unroll
        for (int o = 16; o; o >>= 1) s += __shfl_xor_sync(0xffffffffu, s, o);
        if (lane == 0) kc[W512] = s + __ldg(bb);
    }
}

// ---------------------------------------------------------------------------
// p GEMVs over feat and shuf, writing interleaved p4 = (pfa,pfb,psa,psb).
// Warp per node; feat nodes write .x/.y, shuf nodes write .z/.w.
// ---------------------------------------------------------------------------
__global__ __launch_bounds__(512) void p_both_kernel(
    const float* __restrict__ feat, const float* __restrict__ shuf,
    const float* __restrict__ u, float4* __restrict__ p4, int n)
{
    __shared__ __align__(16) float su[2 * IN_DIM];
    for (int i = threadIdx.x; i < 2 * IN_DIM; i += 512) su[i] = u[i];
    __syncthreads();

    int warp = threadIdx.x >> 5, lane = threadIdx.x & 31;
    int idx = blockIdx.x * 16 + warp;          // 0 .. 2n-1
    if (idx >= 2 * n) return;
    const float* X;
    int v;
    int is_shuf;
    if (idx < n) { X = feat; v = idx;     is_shuf = 0; }
    else         { X = shuf; v = idx - n; is_shuf = 1; }

    const float4* x4 = (const float4*)(X + (size_t)v * IN_DIM);
    const float4* ua4 = (const float4*)su;
    const float4* ub4 = (const float4*)(su + IN_DIM);
    float sa = 0.f, sb = 0.f;
    #pragma unroll
    for (int j = 0; j < 4; j++) {
        float4 x = x4[lane + 32 * j];
        float4 a = ua4[lane + 32 * j];
        float4 b = ub4[lane + 32 * j];
        sa += x.x * a.x + x.y * a.y + x.z * a.z + x.w * a.w;
        sb += x.x * b.x + x.y * b.y + x.z * b.z + x.w * b.w;
    }
    #pragma unroll
    for (int o = 16; o; o >>= 1) {
        sa += __shfl_xor_sync(0xffffffffu, sa, o);
        sb += __shfl_xor_sync(0xffffffffu, sb, o);
    }
    if (lane == 0) {
        float2* dst = (float2*)&p4[v] + is_shuf;   // .xy or .zw
        *dst = make_float2(sa, sb);
    }
}

// ---------------------------------------------------------------------------
// Scatter with vector reductions. blockIdx.y: 0 = list2 -> accA (q0,q2),
//                                            1 = list1 -> accB (q1,q3)
// One float4 p-load + one red.v2 per edge.
// ---------------------------------------------------------------------------
__global__ __launch_bounds__(256) void scatter_v2_kernel(
    const int* __restrict__ src2, const int* __restrict__ dst2, int ne2,
    const int* __restrict__ src1, const int* __restrict__ dst1, int ne1,
    const float4* __restrict__ p4, float2* __restrict__ accA,
    float2* __restrict__ accB)
{
    const int* src; const int* dst; float2* acc; int ne; int sel;
    if (blockIdx.y == 0) { src = src2; dst = dst2; ne = ne2; acc = accA; sel = 0; }
    else                 { src = src1; dst = dst1; ne = ne1; acc = accB; sel = 1; }

    int e0 = (blockIdx.x * 256 + threadIdx.x) * 4;
    if (e0 + 3 < ne) {
        int4 s = *(const int4*)(src + e0);
        int4 d = *(const int4*)(dst + e0);
        float4 px = __ldg(&p4[s.x]);
        float4 py = __ldg(&p4[s.y]);
        float4 pz = __ldg(&p4[s.z]);
        float4 pw = __ldg(&p4[s.w]);
        if (sel == 0) {
            red_v2(&acc[d.x], px.x, px.z);
            red_v2(&acc[d.y], py.x, py.z);
            red_v2(&acc[d.z], pz.x, pz.z);
            red_v2(&acc[d.w], pw.x, pw.z);
        } else {
            red_v2(&acc[d.x], px.y, px.w);
            red_v2(&acc[d.y], py.y, py.w);
            red_v2(&acc[d.z], pz.y, pz.w);
            red_v2(&acc[d.w], pw.y, pw.w);
        }
    } else {
        for (int e = e0; e < ne; e++) {
            float4 pv = __ldg(&p4[src[e]]);
            if (sel == 0) red_v2(&acc[dst[e]], pv.x, pv.z);
            else          red_v2(&acc[dst[e]], pv.y, pv.w);
        }
    }
}

// ---------------------------------------------------------------------------
// Finalize: de-interleave acc into the four output quarters, add constants.
// ---------------------------------------------------------------------------
__global__ void finalize_kernel(const float2* __restrict__ accA,
                                const float2* __restrict__ accB,
                                const float* __restrict__ kc,
                                float* __restrict__ out, int n)
{
    int i = blockIdx.x * 256 + threadIdx.x;
    if (i < n) {
        float k1 = __ldg(&kc[0]), k2 = __ldg(&kc[1]);
        float2 a = accA[i];
        float2 b = accB[i];
        out[i]         = a.x + k1;   // sc1 = h2.v1
        out[n + i]     = b.x + k2;   // sc2 = h1.v2
        out[2 * n + i] = a.y + k1;   // sc3 = h4.v1
        out[3 * n + i] = b.y + k2;   // sc4 = h3.v2
    }
}

// ---------------------------------------------------------------------------
// Launch
// ---------------------------------------------------------------------------
extern "C" void kernel_launch(void* const* d_in, const int* in_sizes, int n_in,
                              void* d_out, int out_size)
{
    const float* feat = (const float*)d_in[0];
    const float* shuf = (const float*)d_in[1];
    const int*   src1 = (const int*)d_in[2];
    const int*   dst1 = (const int*)d_in[3];
    const int*   src2 = (const int*)d_in[4];
    const int*   dst2 = (const int*)d_in[5];
    const float* W1   = (const float*)d_in[6];
    const float* b1   = (const float*)d_in[7];
    const float* W2   = (const float*)d_in[8];
    const float* b2   = (const float*)d_in[9];
    const float* Wb   = (const float*)d_in[10];
    const float* bb   = (const float*)d_in[11];
    float* out = (float*)d_out;

    const int n   = in_sizes[0] / IN_DIM;   // 100000
    const int ne1 = in_sizes[2];
    const int ne2 = in_sizes[4];

    void* p;
    cudaGetSymbolAddress(&p, g_zero);
    int*    deg  = (int*)p;
    float*  wf   = (float*)((int*)p + OFF_WF);
    float*  cpre = (float*)((int*)p + OFF_CPRE);
    int*    bar  = (int*)p + OFF_BAR;
    float2* accA = (float2*)((int*)p + OFF_ACC);
    float2* accB = accA + NN;
    cudaGetSymbolAddress(&p, g_v);  float* v  = (float*)p;
    cudaGetSymbolAddress(&p, g_u);  float* u  = (float*)p;
    cudaGetSymbolAddress(&p, g_k);  float* kc = (float*)p;
    cudaGetSymbolAddress(&p, g_p4); float4* p4 = (float4*)p;

    // 0) zero deg+wf+cpre+bar+acc with one memset (~4.2 MB)
    cudaMemsetAsync(deg, 0, (size_t)ZERO_INTS * sizeof(int));

    // 1) out-degree histograms (both lists, one launch)
    int gp1 = (ne1 / 4 + 255) / 256, gp2 = (ne2 / 4 + 255) / 256;
    {
        dim3 grid(gp1 > gp2 ? gp1 : gp2, 2);
        hist_both<<<grid, 256>>>(src1, ne1, src2, ne2, deg);
    }

    // 2) weighted row-sums of feat
    wf_kernel<<<1024, 256>>>(feat, deg, deg + NN, wf, n);

    // 3) fused tiny chain -> u, kc
    chain_kernel<<<128, 128>>>(W1, W2, Wb, b1, b2, bb, wf, cpre, v, u, kc,
                               bar, 1.0f / (float)n);

    // 4) p projections for feat+shuf, interleaved p4
    p_both_kernel<<<(2 * n + 15) / 16, 512>>>(feat, shuf, u, p4, n);

    // 5) scatter with v2 reductions (both lists, one launch)
    {
        dim3 grid(gp1 > gp2 ? gp1 : gp2, 2);
        scatter_v2_kernel<<<grid, 256>>>(src2, dst2, ne2, src1, dst1, ne1,
                                         p4, accA, accB);
    }

    // 6) finalize: acc + k -> out quarters
    finalize_kernel<<<(n + 255) / 256, 256>>>(accA, accB, kc, out, n);
}